// round 7
// baseline (speedup 1.0000x reference)
#include <cuda_runtime.h>
#include <cuda_fp16.h>

// LBP forward: out = 7.5 + 0.5 * sum_p 2^p * tanh(5*(samp_p - cen_p))
//
// Two kernels:
//  1) stage: input (32,64,56,56) f32 -> zero-padded fp16 buffer [n][c][58][64]
//     (row r stored at r+1, col w stored at w+4; pads are exact zeros, which
//      matches the reference's zero padding).
//  2) main: thread = (n, f, 4-row block, 4-col quad) = 16 outputs.
//     Padding removes ALL bounds checks: center = aligned half2-pair loads,
//     sample = 4 scalar half loads at the (dy,dx)-folded address.
//     Taps with (dy,dx)==(0,0) contribute tanh(0)=0 and are skipped.

#define N_  32
#define D_  64
#define H_  56
#define W_  56
#define F_  128
#define P_  4
#define HW_ (H_ * W_)
#define PW  64
#define PH  58
#define PPLANE (PW * PH)

__device__ __half g_pad[N_ * D_ * PPLANE];   // 15.2 MB staged fp16 input

#define STAGE_TOTAL (N_ * D_ * PH * (PW / 2))   // one thread per half2

__global__ __launch_bounds__(256) void lbp_stage_kernel(const float* __restrict__ in)
{
    int idx = blockIdx.x * 256 + threadIdx.x;
    if (idx >= STAGE_TOTAL) return;
    int wc = idx & 31;          // half2 index within row (PW/2 = 32)
    int t  = idx >> 5;
    int r  = t % PH;
    t /= PH;                    // t = n*D + c  (plane index)
    int row = r - 1;
    int w0  = wc * 2 - 4;
    float a = 0.f, b = 0.f;
    if (row >= 0 && row < H_) {
        const float* rp = in + (size_t)t * HW_ + row * W_;
        if (w0 >= 0 && w0 < W_)         a = rp[w0];
        if (w0 + 1 >= 0 && w0 + 1 < W_) b = rp[w0 + 1];
    }
    reinterpret_cast<__half2*>(g_pad)[idx] = __floats2half2_rn(a, b);
}

__device__ __forceinline__ __half2 tanh_h2(__half2 x) {
    unsigned v = *reinterpret_cast<unsigned*>(&x);
    asm("tanh.approx.f16x2 %0, %0;" : "+r"(v));
    return *reinterpret_cast<__half2*>(&v);
}

#define RB_ 14     // 4-row blocks
#define WQ_ 14     // 4-col quads
#define TOTAL_ (N_ * F_ * RB_ * WQ_)   // 802,816 threads

__global__ __launch_bounds__(256) void lbp_main_kernel(
    const int* __restrict__ kern,   // (F,P,2)
    const int* __restrict__ pm,     // (F,P)
    float*     __restrict__ out)
{
    int idx = blockIdx.x * 256 + threadIdx.x;
    if (idx >= TOTAL_) return;

    int wq = idx % WQ_;
    int t  = idx / WQ_;
    int rb = t % RB_;
    t /= RB_;
    int f  = t & (F_ - 1);
    int n  = t >> 7;

    int r0 = rb * 4;
    int w  = wq * 4;

    int4 pmv = *reinterpret_cast<const int4*>(pm + f * P_);
    int4 k01 = *reinterpret_cast<const int4*>(kern + f * P_ * 2);
    int4 k23 = *reinterpret_cast<const int4*>(kern + f * P_ * 2 + 4);
    int cs[4]  = {pmv.x, pmv.y, pmv.z, pmv.w};
    int dys[4] = {k01.x - 1, k01.z - 1, k23.x - 1, k23.z - 1};
    int dxs[4] = {k01.y - 1, k01.w - 1, k23.y - 1, k23.w - 1};

    const __half* __restrict__ base = g_pad + (size_t)n * D_ * PPLANE;
    const __half2 five = __floats2half2_rn(5.f, 5.f);

    __half2 z = __floats2half2_rn(0.f, 0.f);
    __half2 acc[8];                       // [row j][lo/hi pair]
#pragma unroll
    for (int j = 0; j < 8; j++) acc[j] = z;

#pragma unroll
    for (int p = 0; p < P_; p++) {
        int dy = dys[p], dx = dxs[p];
        if ((dy | dx) == 0) continue;     // tanh(0) == 0: tap is a no-op

        // center at padded (r0+1, w+4); sample at center + dy rows + dx cols
        const __half* __restrict__ cp = base + cs[p] * PPLANE + (r0 + 1) * PW + (w + 4);
        const __half* __restrict__ sp = cp + dy * PW + dx;

        float wpf = 0.5f * (float)(1 << p);
        __half2 wp2 = __floats2half2_rn(wpf, wpf);

#pragma unroll
        for (int j = 0; j < 4; j++) {
            const __half2* crow = reinterpret_cast<const __half2*>(cp + j * PW);
            __half2 c01 = crow[0];
            __half2 c23 = crow[1];
            const __half* sr = sp + j * PW;
            __half2 s01 = __halves2half2(sr[0], sr[1]);
            __half2 s23 = __halves2half2(sr[2], sr[3]);
            __half2 d01 = __hmul2(__hsub2(s01, c01), five);
            __half2 d23 = __hmul2(__hsub2(s23, c23), five);
            acc[j * 2 + 0] = __hfma2(wp2, tanh_h2(d01), acc[j * 2 + 0]);
            acc[j * 2 + 1] = __hfma2(wp2, tanh_h2(d23), acc[j * 2 + 1]);
        }
    }

    float* o = out + ((size_t)(n * F_ + f) * HW_ + r0 * W_ + w);
#pragma unroll
    for (int j = 0; j < 4; j++) {
        float2 lo = __half22float2(acc[j * 2 + 0]);
        float2 hi = __half22float2(acc[j * 2 + 1]);
        *reinterpret_cast<float4*>(o + j * W_) =
            make_float4(7.5f + lo.x, 7.5f + lo.y, 7.5f + hi.x, 7.5f + hi.y);
    }
}

extern "C" void kernel_launch(void* const* d_in, const int* in_sizes, int n_in,
                              void* d_out, int out_size)
{
    const float* in   = (const float*)d_in[0];
    const int*   kern = (const int*)d_in[1];
    const int*   pm   = (const int*)d_in[2];
    float*       out  = (float*)d_out;

    lbp_stage_kernel<<<(STAGE_TOTAL + 255) / 256, 256>>>(in);
    lbp_main_kernel<<<(TOTAL_ + 255) / 256, 256>>>(kern, pm, out);
}

// round 8
// speedup vs baseline: 1.2767x; 1.2767x over previous
#include <cuda_runtime.h>
#include <cuda_fp16.h>

// LBP forward: out = 7.5 + 0.5 * sum_p 2^p * tanh(5*(samp_p - cen_p))
//
// Stage: three pre-shifted, zero-padded fp16 copies, scaled by 5:
//   copy_s[plane][r][i] = 5 * x[plane][r-1][i-5+s],  s in {0,1,2}, zero outside.
// Then for a tap with shift (dy,dx), the 4-wide sample window starting at
// x-col w+dx is copy_{dx+1} at padded (row r0+1+j+dy, col w+4) — the SAME
// 8B-aligned column for every dx. Center is copy_1 at (r0+1+j, w+4).
// => every main-kernel load is one aligned LDG.64, no bounds checks at all.
// The *5 is folded into staging; (dy,dx)==(0,0) taps are skipped (tanh(0)=0).

#define N_  32
#define D_  64
#define H_  56
#define W_  56
#define F_  128
#define P_  4
#define HW_ (H_ * W_)
#define PW  64
#define PH  58
#define PPLANE (PW * PH)
#define NPLANES (N_ * D_)                 // 2048
#define SVOL ((size_t)NPLANES * PPLANE)   // halfs per copy

__device__ __half g3[3 * N_ * D_ * PPLANE];   // 45.6 MB

// ---------------- stage ----------------
#define STAGE_TOTAL (NPLANES * PH * 8)    // thread per 8-half chunk (950,272)

__global__ __launch_bounds__(256) void lbp_stage_kernel(const float* __restrict__ in)
{
    int idx = blockIdx.x * 256 + threadIdx.x;
    if (idx >= STAGE_TOTAL) return;
    int k  = idx & 7;            // chunk: padded cols 8k..8k+7
    int t  = idx >> 3;
    int r  = t % PH;
    int pl = t / PH;
    int row = r - 1;
    int c0  = 8 * k;

    float wv[10];                // x cols c0-5 .. c0+4
#pragma unroll
    for (int i = 0; i < 10; i++) wv[i] = 0.f;

    if (row >= 0 && row < H_) {
        const float* __restrict__ rp = in + (size_t)pl * HW_ + row * W_;
        int xa = c0 - 5;
        if (xa >= 0) wv[0] = rp[xa];                       // xa <= 51 always ok
        if (k >= 1) {                                      // cols c0-4..c0-1
            float4 a = *reinterpret_cast<const float4*>(rp + c0 - 4);
            wv[1] = a.x; wv[2] = a.y; wv[3] = a.z; wv[4] = a.w;
        }
        if (c0 + 3 < W_) {                                 // cols c0..c0+3
            float4 b = *reinterpret_cast<const float4*>(rp + c0);
            wv[5] = b.x; wv[6] = b.y; wv[7] = b.z; wv[8] = b.w;
        }
        if (c0 + 4 < W_) wv[9] = rp[c0 + 4];
    }

#pragma unroll
    for (int s = 0; s < 3; s++) {
        __half2 h[4];
#pragma unroll
        for (int q = 0; q < 4; q++)
            h[q] = __floats2half2_rn(5.f * wv[s + 2 * q], 5.f * wv[s + 2 * q + 1]);
        __half* dst = g3 + (size_t)s * SVOL + (size_t)pl * PPLANE + r * PW + c0;
        *reinterpret_cast<uint4*>(dst) = *reinterpret_cast<uint4*>(h);
    }
}

// ---------------- main ----------------
__device__ __forceinline__ __half2 tanh_h2(__half2 x) {
    unsigned v = *reinterpret_cast<unsigned*>(&x);
    asm("tanh.approx.f16x2 %0, %0;" : "+r"(v));
    return *reinterpret_cast<__half2*>(&v);
}

#define RB_ 14     // 4-row blocks
#define WQ_ 14     // 4-col quads
#define TOTAL_ (N_ * F_ * RB_ * WQ_)   // 802,816 threads

__global__ __launch_bounds__(256) void lbp_main_kernel(
    const int* __restrict__ kern,   // (F,P,2)
    const int* __restrict__ pm,     // (F,P)
    float*     __restrict__ out)
{
    int idx = blockIdx.x * 256 + threadIdx.x;
    if (idx >= TOTAL_) return;

    int wq = idx % WQ_;
    int t  = idx / WQ_;
    int rb = t % RB_;
    t /= RB_;
    int f  = t & (F_ - 1);
    int n  = t >> 7;

    int r0 = rb * 4;
    int w  = wq * 4;

    int4 pmv = *reinterpret_cast<const int4*>(pm + f * P_);
    int4 k01 = *reinterpret_cast<const int4*>(kern + f * P_ * 2);
    int4 k23 = *reinterpret_cast<const int4*>(kern + f * P_ * 2 + 4);
    int cs[4]  = {pmv.x, pmv.y, pmv.z, pmv.w};
    int dys[4] = {k01.x - 1, k01.z - 1, k23.x - 1, k23.z - 1};
    int dxs[4] = {k01.y - 1, k01.w - 1, k23.y - 1, k23.w - 1};

    const size_t nbase = (size_t)n * D_ * PPLANE;
    const int    rcoff = (r0 + 1) * PW + (w + 4);   // padded (row,col) offset

    __half2 z = __floats2half2_rn(0.f, 0.f);
    __half2 acc[8];
#pragma unroll
    for (int j = 0; j < 8; j++) acc[j] = z;

#pragma unroll
    for (int p = 0; p < P_; p++) {
        int dy = dys[p], dx = dxs[p];
        if ((dy | dx) == 0) continue;            // tanh(0) == 0

        const __half* __restrict__ cp =
            g3 + SVOL + nbase + (size_t)cs[p] * PPLANE + rcoff;
        const __half* __restrict__ sp =
            g3 + (size_t)(dx + 1) * SVOL + nbase + (size_t)cs[p] * PPLANE
               + rcoff + dy * PW;

        float wpf = 0.5f * (float)(1 << p);
        __half2 wp2 = __floats2half2_rn(wpf, wpf);

#pragma unroll
        for (int j = 0; j < 4; j++) {
            uint2 cv = *reinterpret_cast<const uint2*>(cp + j * PW);
            uint2 sv = *reinterpret_cast<const uint2*>(sp + j * PW);
            __half2 c01 = *reinterpret_cast<__half2*>(&cv.x);
            __half2 c23 = *reinterpret_cast<__half2*>(&cv.y);
            __half2 s01 = *reinterpret_cast<__half2*>(&sv.x);
            __half2 s23 = *reinterpret_cast<__half2*>(&sv.y);
            acc[j * 2 + 0] = __hfma2(wp2, tanh_h2(__hsub2(s01, c01)), acc[j * 2 + 0]);
            acc[j * 2 + 1] = __hfma2(wp2, tanh_h2(__hsub2(s23, c23)), acc[j * 2 + 1]);
        }
    }

    float* o = out + ((size_t)(n * F_ + f) * HW_ + r0 * W_ + w);
#pragma unroll
    for (int j = 0; j < 4; j++) {
        float2 lo = __half22float2(acc[j * 2 + 0]);
        float2 hi = __half22float2(acc[j * 2 + 1]);
        *reinterpret_cast<float4*>(o + j * W_) =
            make_float4(7.5f + lo.x, 7.5f + lo.y, 7.5f + hi.x, 7.5f + hi.y);
    }
}

extern "C" void kernel_launch(void* const* d_in, const int* in_sizes, int n_in,
                              void* d_out, int out_size)
{
    const float* in   = (const float*)d_in[0];
    const int*   kern = (const int*)d_in[1];
    const int*   pm   = (const int*)d_in[2];
    float*       out  = (float*)d_out;

    lbp_stage_kernel<<<(STAGE_TOTAL + 255) / 256, 256>>>(in);
    lbp_main_kernel<<<(TOTAL_ + 255) / 256, 256>>>(kern, pm, out);
}

// round 9
// speedup vs baseline: 1.3529x; 1.0597x over previous
#include <cuda_runtime.h>
#include <cuda_fp16.h>

// LBP forward: out = 7.5 + 0.5 * sum_p 2^p * tanh(5*(samp_p - cen_p))
//
// Stage: ONE zero-padded fp16 copy scaled by 5: pad[pl][r][j] = 5*x[pl][r-1][j-4]
//   (PW=64 cols: 4 left pad, 56 data, 4 right pad; PH=58 rows).
// Main: thread = (n, f, row-pair, 8-wide span) = 16 outputs.
//   Center cols (padded) w+4..w+11 = two aligned LDG.64 per row.
//   dx=+-1 sample windows come from the SAME registers via funnel shifts
//   (u32 pair >> 16 == shift by one half) plus one LDG.32 edge word per row.
//   dy=+-1 reuses one center row, loads one new row. Zero bounds checks.
//   (dy,dx)==(0,0) taps skipped (tanh(0)=0).

#define N_  32
#define D_  64
#define H_  56
#define W_  56
#define F_  128
#define P_  4
#define HW_ (H_ * W_)
#define PW  64
#define PH  58
#define PPLANE (PW * PH)
#define NPLANES (N_ * D_)

__device__ __half g1[NPLANES * PPLANE];   // 15.2 MB

// ---------------- stage ----------------
#define STAGE_TOTAL (NPLANES * PH * 8)    // one thread per 8-half chunk

__global__ __launch_bounds__(256) void lbp_stage_kernel(const float* __restrict__ in)
{
    int idx = blockIdx.x * 256 + threadIdx.x;
    if (idx >= STAGE_TOTAL) return;
    int k  = idx & 7;
    int t  = idx >> 3;
    int r  = t % PH;
    int pl = t / PH;
    int row = r - 1;

    float v[8];
#pragma unroll
    for (int i = 0; i < 8; i++) v[i] = 0.f;

    if (row >= 0 && row < H_) {
        const float* __restrict__ rp = in + (size_t)pl * HW_ + row * W_;
        if (k >= 1) {                       // x cols 8k-4..8k-1
            float4 a = *reinterpret_cast<const float4*>(rp + 8 * k - 4);
            v[0] = a.x; v[1] = a.y; v[2] = a.z; v[3] = a.w;
        }
        if (k <= 6) {                       // x cols 8k..8k+3
            float4 b = *reinterpret_cast<const float4*>(rp + 8 * k);
            v[4] = b.x; v[5] = b.y; v[6] = b.z; v[7] = b.w;
        }
    }

    __half2 h[4];
#pragma unroll
    for (int q = 0; q < 4; q++)
        h[q] = __floats2half2_rn(5.f * v[2 * q], 5.f * v[2 * q + 1]);
    __half* dst = g1 + (size_t)pl * PPLANE + r * PW + 8 * k;
    *reinterpret_cast<uint4*>(dst) = *reinterpret_cast<uint4*>(h);
}

// ---------------- main ----------------
__device__ __forceinline__ __half2 tanh_h2u(unsigned v) {
    asm("tanh.approx.f16x2 %0, %0;" : "+r"(v));
    return *reinterpret_cast<__half2*>(&v);
}
__device__ __forceinline__ __half2 u2h(unsigned v) {
    return *reinterpret_cast<__half2*>(&v);
}

#define RP_ 28     // row pairs
#define WS_ 7      // 8-wide spans
#define TOTAL_ (N_ * F_ * RP_ * WS_)   // 802,816 threads

struct HV4 { unsigned v[4]; };   // 4 half2 = 8 halfs (padded cols w+4..w+11 etc.)

__device__ __forceinline__ HV4 mk4(uint2 A, uint2 B) {
    HV4 r; r.v[0] = A.x; r.v[1] = A.y; r.v[2] = B.x; r.v[3] = B.y; return r;
}
// window shifted one half LEFT (cols w+3..w+10): needs v1 (cols w+2,w+3)
__device__ __forceinline__ HV4 shl(unsigned v1, uint2 A, uint2 B) {
    HV4 r;
    r.v[0] = __funnelshift_r(v1,  A.x, 16);
    r.v[1] = __funnelshift_r(A.x, A.y, 16);
    r.v[2] = __funnelshift_r(A.y, B.x, 16);
    r.v[3] = __funnelshift_r(B.x, B.y, 16);
    return r;
}
// window shifted one half RIGHT (cols w+5..w+12): needs v6 (cols w+12,w+13)
__device__ __forceinline__ HV4 shr_(uint2 A, uint2 B, unsigned v6) {
    HV4 r;
    r.v[0] = __funnelshift_r(A.x, A.y, 16);
    r.v[1] = __funnelshift_r(A.y, B.x, 16);
    r.v[2] = __funnelshift_r(B.x, B.y, 16);
    r.v[3] = __funnelshift_r(B.y, v6,  16);
    return r;
}

__global__ __launch_bounds__(256) void lbp_main_kernel(
    const int* __restrict__ kern,   // (F,P,2)
    const int* __restrict__ pm,     // (F,P)
    float*     __restrict__ out)
{
    int idx = blockIdx.x * 256 + threadIdx.x;
    if (idx >= TOTAL_) return;

    int ws = idx % WS_;
    int t  = idx / WS_;
    int rp = t % RP_;
    t /= RP_;
    int f  = t & (F_ - 1);
    int n  = t >> 7;

    int r0 = rp * 2;
    int w  = ws * 8;                 // padded base col; output x cols w..w+7

    int4 pmv = *reinterpret_cast<const int4*>(pm + f * P_);
    int4 k01 = *reinterpret_cast<const int4*>(kern + f * P_ * 2);
    int4 k23 = *reinterpret_cast<const int4*>(kern + f * P_ * 2 + 4);
    int cs[4]  = {pmv.x, pmv.y, pmv.z, pmv.w};
    int dys[4] = {k01.x - 1, k01.z - 1, k23.x - 1, k23.z - 1};
    int dxs[4] = {k01.y - 1, k01.w - 1, k23.y - 1, k23.w - 1};

    const __half* __restrict__ nb = g1 + (size_t)n * D_ * PPLANE;
    int roff = (r0 + 1) * PW + w;    // padded (row r0, col w)

    __half2 z = __floats2half2_rn(0.f, 0.f);
    __half2 acc0[4] = {z, z, z, z};
    __half2 acc1[4] = {z, z, z, z};

#pragma unroll
    for (int p = 0; p < P_; p++) {
        int dy = dys[p], dx = dxs[p];
        if ((dy | dx) == 0) continue;

        const __half* __restrict__ row0 = nb + (size_t)cs[p] * PPLANE + roff;
        const __half* __restrict__ row1 = row0 + PW;

        // center registers: cols w+4..w+11 of rows r0, r1
        uint2 A0 = *reinterpret_cast<const uint2*>(row0 + 4);
        uint2 B0 = *reinterpret_cast<const uint2*>(row0 + 8);
        uint2 A1 = *reinterpret_cast<const uint2*>(row1 + 4);
        uint2 B1 = *reinterpret_cast<const uint2*>(row1 + 8);

        HV4 s0, s1;
        if (dy == 0) {
            // dx != 0 guaranteed here
            if (dx < 0) {
                unsigned e0 = *reinterpret_cast<const unsigned*>(row0 + 2);
                unsigned e1 = *reinterpret_cast<const unsigned*>(row1 + 2);
                s0 = shl(e0, A0, B0);
                s1 = shl(e1, A1, B1);
            } else {
                unsigned e0 = *reinterpret_cast<const unsigned*>(row0 + 12);
                unsigned e1 = *reinterpret_cast<const unsigned*>(row1 + 12);
                s0 = shr_(A0, B0, e0);
                s1 = shr_(A1, B1, e1);
            }
        } else {
            const __half* __restrict__ nrow = (dy < 0) ? row0 - PW : row1 + PW;
            uint2 An = *reinterpret_cast<const uint2*>(nrow + 4);
            uint2 Bn = *reinterpret_cast<const uint2*>(nrow + 8);
            // sample row for out-row0 / out-row1
            const __half* sr0p = (dy < 0) ? nrow : row1;
            const __half* sr1p = (dy < 0) ? row0 : nrow;
            uint2 SA0 = (dy < 0) ? An : A1,  SB0 = (dy < 0) ? Bn : B1;
            uint2 SA1 = (dy < 0) ? A0 : An,  SB1 = (dy < 0) ? B0 : Bn;
            if (dx == 0) {
                s0 = mk4(SA0, SB0);
                s1 = mk4(SA1, SB1);
            } else if (dx < 0) {
                unsigned e0 = *reinterpret_cast<const unsigned*>(sr0p + 2);
                unsigned e1 = *reinterpret_cast<const unsigned*>(sr1p + 2);
                s0 = shl(e0, SA0, SB0);
                s1 = shl(e1, SA1, SB1);
            } else {
                unsigned e0 = *reinterpret_cast<const unsigned*>(sr0p + 12);
                unsigned e1 = *reinterpret_cast<const unsigned*>(sr1p + 12);
                s0 = shr_(SA0, SB0, e0);
                s1 = shr_(SA1, SB1, e1);
            }
        }

        float wpf = 0.5f * (float)(1 << p);
        __half2 wp2 = __floats2half2_rn(wpf, wpf);
        HV4 c0 = mk4(A0, B0), c1 = mk4(A1, B1);
#pragma unroll
        for (int q = 0; q < 4; q++) {
            __half2 d0 = __hsub2(u2h(s0.v[q]), u2h(c0.v[q]));
            __half2 d1 = __hsub2(u2h(s1.v[q]), u2h(c1.v[q]));
            acc0[q] = __hfma2(wp2, tanh_h2u(*reinterpret_cast<unsigned*>(&d0)), acc0[q]);
            acc1[q] = __hfma2(wp2, tanh_h2u(*reinterpret_cast<unsigned*>(&d1)), acc1[q]);
        }
    }

    float* o = out + ((size_t)(n * F_ + f) * HW_ + r0 * W_ + w);
#pragma unroll
    for (int r = 0; r < 2; r++) {
        __half2* a = r ? acc1 : acc0;
        float* orow = o + r * W_;
        float2 q0 = __half22float2(a[0]), q1 = __half22float2(a[1]);
        float2 q2 = __half22float2(a[2]), q3 = __half22float2(a[3]);
        *reinterpret_cast<float4*>(orow) =
            make_float4(7.5f + q0.x, 7.5f + q0.y, 7.5f + q1.x, 7.5f + q1.y);
        *reinterpret_cast<float4*>(orow + 4) =
            make_float4(7.5f + q2.x, 7.5f + q2.y, 7.5f + q3.x, 7.5f + q3.y);
    }
}

extern "C" void kernel_launch(void* const* d_in, const int* in_sizes, int n_in,
                              void* d_out, int out_size)
{
    const float* in   = (const float*)d_in[0];
    const int*   kern = (const int*)d_in[1];
    const int*   pm   = (const int*)d_in[2];
    float*       out  = (float*)d_out;

    lbp_stage_kernel<<<(STAGE_TOTAL + 255) / 256, 256>>>(in);
    lbp_main_kernel<<<(TOTAL_ + 255) / 256, 256>>>(kern, pm, out);
}